// round 8
// baseline (speedup 1.0000x reference)
#include <cuda_runtime.h>
#include <math.h>

#define NN    400000
#define NE    1600000
#define FIN   100
#define EMB   128
#define SORTK 64
#define NG    11
#define DCAT  385
#define DENSE 3584
#define FC1IN 39424

typedef unsigned long long ull;
typedef unsigned int uint;

/* ---------------- scratch (static device memory; no allocations) ------------- */
__device__ float g_h [NN*EMB];
__device__ float g_x1[NN*EMB];
__device__ float g_x2[NN*EMB];
__device__ float g_x3[NN*EMB];
__device__ float g_x4[NN];
__device__ float g_h4[NN];
__device__ float g_dis[NN];
__device__ int   g_cnt[NN];
__device__ int   g_off[NN];
__device__ int   g_cur[NN];
__device__ int2  g_csr[NE];
__device__ int   g_bsum[1024];
__device__ int   g_gcnt[NG];
__device__ int   g_gstart[NG+1];
__device__ int   g_sel[NG*SORTK];
__device__ float g_h5[NG*64*SORTK];
__device__ float g_emb[FC1IN];
__device__ float g_out128[128];

__device__ __forceinline__ float* bufById(int id) {
  return (id==1) ? g_x1 : (id==2) ? g_x2 : g_x3;
}

/* ---------------- f32x2 + cp.async helpers ------------------------------------ */
__device__ __forceinline__ void ffma2(ull& d, ull a, ull b) {
  asm("fma.rn.f32x2 %0, %1, %2, %0;" : "+l"(d) : "l"(a), "l"(b));
}
__device__ __forceinline__ ull dup2(float x) {
  ull r; asm("mov.b64 %0, {%1, %1};" : "=l"(r) : "f"(x)); return r;
}
__device__ __forceinline__ float2 unpack2(ull v) {
  float2 f; asm("mov.b64 {%0, %1}, %2;" : "=f"(f.x), "=f"(f.y) : "l"(v)); return f;
}
__device__ __forceinline__ uint smem_u32(const void* p) {
  uint a;
  asm("{ .reg .u64 t; cvta.to.shared.u64 t, %1; cvt.u32.u64 %0, t; }" : "=r"(a) : "l"(p));
  return a;
}
__device__ __forceinline__ void cpasync16(uint sm, const void* g) {
  asm volatile("cp.async.ca.shared.global [%0], [%1], 16;" :: "r"(sm), "l"(g));
}
#define CP_COMMIT() asm volatile("cp.async.commit_group;" ::: "memory")
#define CP_WAIT1()  asm volatile("cp.async.wait_group 1;" ::: "memory")
#define CP_WAIT0()  asm volatile("cp.async.wait_group 0;" ::: "memory")

/* ---------------- init / degree / CSR build ---------------------------------- */
__global__ void k_init() {
  int i = blockIdx.x*blockDim.x + threadIdx.x;
  if (i < NN) { g_cnt[i] = 0; g_cur[i] = 0; }
  if (i < NG) g_gcnt[i] = 0;
  if (i < NG*SORTK) g_sel[i] = -1;
}

__global__ void k_edge_count(const int* __restrict__ ei) {
  int e = blockIdx.x*blockDim.x + threadIdx.x;
  if (e >= NE) return;
  int s = ei[e], d = ei[NE + e];
  if (s != d) atomicAdd(&g_cnt[d], 1);
}

__global__ void k_dis() {
  int i = blockIdx.x*blockDim.x + threadIdx.x;
  if (i < NN) g_dis[i] = rsqrtf((float)g_cnt[i] + 1.0f);
}

__global__ void k_scan1() {
  __shared__ int sh[1024];
  int t = threadIdx.x;
  int i = blockIdx.x*1024 + t;
  int v = (i < NN) ? g_cnt[i] : 0;
  sh[t] = v; __syncthreads();
  for (int d = 1; d < 1024; d <<= 1) {
    int u = (t >= d) ? sh[t-d] : 0;
    __syncthreads();
    sh[t] += u;
    __syncthreads();
  }
  if (i < NN) g_off[i] = sh[t] - v;
  if (t == 1023) g_bsum[blockIdx.x] = sh[1023];
}

__global__ void k_scan2(int nb) {
  __shared__ int sh[1024];
  int t = threadIdx.x;
  int v = (t < nb) ? g_bsum[t] : 0;
  sh[t] = v; __syncthreads();
  for (int d = 1; d < 1024; d <<= 1) {
    int u = (t >= d) ? sh[t-d] : 0;
    __syncthreads();
    sh[t] += u;
    __syncthreads();
  }
  if (t < nb) g_bsum[t] = sh[t] - v;
}

__global__ void k_scan3() {
  int i = blockIdx.x*blockDim.x + threadIdx.x;
  if (i < NN) g_off[i] += g_bsum[i >> 10];
}

__global__ void k_scatter(const int* __restrict__ ei) {
  int e = blockIdx.x*blockDim.x + threadIdx.x;
  if (e >= NE) return;
  int s = ei[e], d = ei[NE + e];
  if (s != d) {
    int p = g_off[d] + atomicAdd(&g_cur[d], 1);
    float w = g_dis[s]*g_dis[d];
    g_csr[p] = make_int2(s, __float_as_int(w));
  }
}

__global__ void k_gcount(const int* __restrict__ batch) {
  __shared__ int loc[NG];
  if (threadIdx.x < NG) loc[threadIdx.x] = 0;
  __syncthreads();
  int i = blockIdx.x*blockDim.x + threadIdx.x;
  if (i < NN) atomicAdd(&loc[batch[i]], 1);
  __syncthreads();
  if (threadIdx.x < NG) atomicAdd(&g_gcnt[threadIdx.x], loc[threadIdx.x]);
}

__global__ void k_gstart() {
  if (threadIdx.x == 0 && blockIdx.x == 0) {
    int a = 0;
    for (int g = 0; g < NG; ++g) { g_gstart[g] = a; a += g_gcnt[g]; }
    g_gstart[NG] = a;
  }
}

/* ---------------- GEMM: FFMA2 + cp.async double buffer ------------------------ */
/* 128x128 tile, 256 threads, 8x8/thread.  dyn smem: 2x(Xs 16KB + Ws 16KB).      */
__global__ __launch_bounds__(256, 2) void k_gemm(const float* __restrict__ Xext, int xbuf,
                                                 const float* __restrict__ W, int K) {
  extern __shared__ float sm[];
  float* XsB[2] = { sm,        sm + 4096 };
  float* WsB[2] = { sm + 8192, sm + 12288 };
  const float* __restrict__ X = Xext ? Xext : bufById(xbuf);
  const int tid = threadIdx.x;
  const int tr  = tid >> 4;
  const int tc  = tid & 15;
  const int r0t = tr * 8;
  const int c0  = tc * 8;
  const int row0 = blockIdx.x * 128;
  const int nc = (K + 31) >> 5;

  ull acc[8][4];
  #pragma unroll
  for (int r = 0; r < 8; ++r)
    #pragma unroll
    for (int j = 0; j < 4; ++j) acc[r][j] = 0ull;

  /* fill chunk c into buffer b (async) */
  auto fill = [&](int c, int b) {
    const int kb = c*32;
    const int kc = min(32, K - kb);
    const int kq = kc >> 2;            /* 8 or 1 */
    float* Xb = XsB[b];
    float* Wb = WsB[b];
    for (int idx = tid; idx < 128*kq; idx += 256) {
      int r = idx / kq, q = idx - r*kq;
      cpasync16(smem_u32(Xb + r*32 + q*4), X + (size_t)(row0 + r)*K + kb + q*4);
    }
    for (int idx = tid; idx < kc*32; idx += 256) {
      int k = idx >> 5, cq = idx & 31;
      cpasync16(smem_u32(Wb + k*128 + cq*4), W + (size_t)(kb + k)*128 + cq*4);
    }
  };

  fill(0, 0); CP_COMMIT();

  for (int c = 0; c < nc; ++c) {
    if (c + 1 < nc) { fill(c+1, (c+1) & 1); CP_COMMIT(); CP_WAIT1(); }
    else            { CP_WAIT0(); }
    __syncthreads();

    const float* Xb = XsB[c & 1];
    const float* Wb = WsB[c & 1];
    const int kc = min(32, K - c*32);
    #pragma unroll 4
    for (int k = 0; k < kc; ++k) {
      ull w[4];
      const ull* wp = (const ull*)(Wb + k*128 + c0);
      w[0] = wp[0]; w[1] = wp[1]; w[2] = wp[2]; w[3] = wp[3];
      #pragma unroll
      for (int r = 0; r < 8; ++r) {
        ull xd = dup2(Xb[(r0t + r)*32 + k]);
        ffma2(acc[r][0], xd, w[0]);
        ffma2(acc[r][1], xd, w[1]);
        ffma2(acc[r][2], xd, w[2]);
        ffma2(acc[r][3], xd, w[3]);
      }
    }
    __syncthreads();
  }

  #pragma unroll
  for (int r = 0; r < 8; ++r) {
    int gr = row0 + r0t + r;
    float2 a0 = unpack2(acc[r][0]), a1 = unpack2(acc[r][1]);
    float2 a2 = unpack2(acc[r][2]), a3 = unpack2(acc[r][3]);
    *(float4*)&g_h[(size_t)gr*EMB + c0]     = make_float4(a0.x, a0.y, a1.x, a1.y);
    *(float4*)&g_h[(size_t)gr*EMB + c0 + 4] = make_float4(a2.x, a2.y, a3.x, a3.y);
  }
}

/* ---------------- aggregation, 64-channel half per pass ----------------------- */
/* one warp per node, lane owns float2; gather half fits L2 (102MB < 126MB).      */
__global__ void k_agg_half(const float* __restrict__ bias, int outId, int half,
                           const float* __restrict__ W4) {
  int n = (blockIdx.x*blockDim.x + threadIdx.x) >> 5;
  if (n >= NN) return;
  int lane = threadIdx.x & 31;
  const int co = (half << 6) + lane*2;

  int b = g_off[n], e = b + g_cnt[n];
  float2 self = *(const float2*)(g_h + (size_t)n*EMB + co);

  float ax = 0.f, ay = 0.f;
  int j = b;
  for (; j + 4 <= e; j += 4) {
    int2 e0 = __ldcs(&g_csr[j]),   e1 = __ldcs(&g_csr[j+1]);
    int2 e2 = __ldcs(&g_csr[j+2]), e3 = __ldcs(&g_csr[j+3]);
    float2 h0 = *(const float2*)(g_h + (size_t)e0.x*EMB + co);
    float2 h1 = *(const float2*)(g_h + (size_t)e1.x*EMB + co);
    float2 h2 = *(const float2*)(g_h + (size_t)e2.x*EMB + co);
    float2 h3 = *(const float2*)(g_h + (size_t)e3.x*EMB + co);
    float w0 = __int_as_float(e0.y), w1 = __int_as_float(e1.y);
    float w2 = __int_as_float(e2.y), w3 = __int_as_float(e3.y);
    ax += w0*h0.x + w1*h1.x + w2*h2.x + w3*h3.x;
    ay += w0*h0.y + w1*h1.y + w2*h2.y + w3*h3.y;
  }
  for (; j < e; ++j) {
    int2 ee = __ldcs(&g_csr[j]);
    float w = __int_as_float(ee.y);
    float2 hv = *(const float2*)(g_h + (size_t)ee.x*EMB + co);
    ax += w*hv.x; ay += w*hv.y;
  }

  float di = g_dis[n]; float sn = di*di;
  float2 bv = *(const float2*)(bias + co);
  float2 o;
  o.x = tanhf(ax + sn*self.x + bv.x);
  o.y = tanhf(ay + sn*self.y + bv.y);
  __stcs((float2*)(bufById(outId) + (size_t)n*EMB + co), o);

  if (W4) {   /* partial h4 = dot(x3_half, W4_half); pass1 accumulates pass0 */
    float2 wv = *(const float2*)(W4 + co);
    float a = o.x*wv.x + o.y*wv.y;
    #pragma unroll
    for (int d = 16; d; d >>= 1) a += __shfl_down_sync(0xffffffffu, a, d);
    if (lane == 0) {
      if (half == 0) g_h4[n] = a;
      else           g_h4[n] += a;
    }
  }
}

/* ---------------- layer 4 aggregation (scalar) -------------------------------- */
__global__ void k_agg4(const float* __restrict__ b4) {
  int n = blockIdx.x*blockDim.x + threadIdx.x;
  if (n >= NN) return;
  float acc = 0.f;
  int b = g_off[n], e = b + g_cnt[n];
  int j = b;
  for (; j + 2 <= e; j += 2) {
    int2 e0 = g_csr[j], e1 = g_csr[j+1];
    float v0 = g_h4[e0.x], v1 = g_h4[e1.x];
    acc += __int_as_float(e0.y)*v0 + __int_as_float(e1.y)*v1;
  }
  if (j < e) {
    int2 e0 = g_csr[j];
    acc += __int_as_float(e0.y)*g_h4[e0.x];
  }
  float di = g_dis[n];
  g_x4[n] = tanhf(acc + g_h4[n]*di*di + b4[0]);
}

/* ---------------- per-graph exact top-64 (desc score, stable by index) -------- */
__device__ __forceinline__ unsigned keyOf(float f) {
  unsigned u = __float_as_uint(f);
  return (u & 0x80000000u) ? ~u : (u | 0x80000000u);
}

__global__ void k_select() {
  const int g = blockIdx.x;
  const int s = g_gstart[g], e = g_gstart[g+1];
  const int n = e - s;
  const int tid = threadIdx.x;
  const int NT = blockDim.x;

  __shared__ int      selIdx[SORTK];
  __shared__ unsigned selKey[SORTK];
  __shared__ int      red[32];
  __shared__ unsigned shPrefix;
  __shared__ int      shRem, shCg;

  if (tid < SORTK) { selIdx[tid] = -1; selKey[tid] = 0u; }
  if (tid == 0)    { shPrefix = 0u; shRem = SORTK; shCg = 0; }
  __syncthreads();

  if (n <= SORTK) {
    if (tid < n) { selIdx[tid] = s + tid; selKey[tid] = keyOf(g_x4[s+tid]); }
    __syncthreads();
  } else {
    for (int bit = 31; bit >= 0; --bit) {
      unsigned cand = shPrefix | (1u << bit);
      unsigned mask = ~((1u << bit) - 1u);
      int c = 0;
      for (int i = s + tid; i < e; i += NT)
        c += ((keyOf(g_x4[i]) & mask) == cand) ? 1 : 0;
      #pragma unroll
      for (int d = 16; d; d >>= 1) c += __shfl_down_sync(0xffffffffu, c, d);
      if ((tid & 31) == 0) red[tid >> 5] = c;
      __syncthreads();
      if (tid == 0) {
        int tot = 0;
        for (int w = 0; w < (NT >> 5); ++w) tot += red[w];
        if (tot >= shRem) shPrefix = cand; else shRem -= tot;
      }
      __syncthreads();
    }
    unsigned Tk = shPrefix;
    for (int i = s + tid; i < e; i += NT) {
      unsigned k = keyOf(g_x4[i]);
      if (k > Tk) {
        int p = atomicAdd(&shCg, 1);
        selIdx[p] = i; selKey[p] = k;
      }
    }
    __syncthreads();
    int cg = shCg;
    int need = SORTK - cg;
    for (int i = s + tid; i < e; i += NT) {
      if (keyOf(g_x4[i]) == Tk) {
        int r = 0;
        for (int j = s; j < i; ++j) r += (keyOf(g_x4[j]) == Tk) ? 1 : 0;
        if (r < need) { selIdx[cg + r] = i; selKey[cg + r] = Tk; }
      }
    }
    __syncthreads();
  }

  if (tid < SORTK) {
    int mi = selIdx[tid];
    if (mi >= 0) {
      unsigned mk = selKey[tid];
      int r = 0;
      for (int j = 0; j < SORTK; ++j) {
        int ij = selIdx[j]; if (ij < 0) continue;
        unsigned kj = selKey[j];
        if (kj > mk || (kj == mk && ij < mi)) ++r;
      }
      g_sel[g*SORTK + r] = mi;
    }
  }
}

/* ---------------- conv5 (385 -> 64 per sorted row) + relu --------------------- */
__global__ void k_conv5(const float* __restrict__ cw5, const float* __restrict__ cb5) {
  __shared__ float row[DCAT];
  int g = blockIdx.x / SORTK, k = blockIdx.x % SORTK;
  int m = g_sel[g*SORTK + k];
  int tid = threadIdx.x;
  for (int d = tid; d < DCAT; d += 128) {
    float v = 0.f;
    if (m >= 0) {
      if      (d < 128) v = g_x1[(size_t)m*EMB + d];
      else if (d < 256) v = g_x2[(size_t)m*EMB + d - 128];
      else if (d < 384) v = g_x3[(size_t)m*EMB + d - 256];
      else              v = g_x4[m];
    }
    row[d] = v;
  }
  __syncthreads();
  if (tid < 64) {
    float acc = cb5[tid];
    const float* w = cw5 + tid*DCAT;
    for (int d = 0; d < DCAT; ++d) acc += w[d]*row[d];
    g_h5[((size_t)g*64 + tid)*SORTK + k] = fmaxf(acc, 0.f);
  }
}

/* ---------------- maxpool(2) + conv6(k=5) + relu -> emb ----------------------- */
__global__ void k_conv6(const float* __restrict__ cw6, const float* __restrict__ cb6) {
  __shared__ float hp[64*32];
  int g = blockIdx.x, tid = threadIdx.x;
  for (int i = tid; i < 64*32; i += 128) {
    int ci = i >> 5, j = i & 31;
    const float* hr = g_h5 + ((size_t)g*64 + ci)*SORTK + 2*j;
    hp[ci*32 + j] = fmaxf(hr[0], hr[1]);
  }
  __syncthreads();
  int o = tid;
  const float* w = cw6 + (size_t)o*64*5;
  for (int l = 0; l < 28; ++l) {
    float acc = cb6[o];
    for (int ci = 0; ci < 64; ++ci) {
      const float* hh = hp + ci*32 + l;
      const float* wc = w + ci*5;
      acc += wc[0]*hh[0] + wc[1]*hh[1] + wc[2]*hh[2] + wc[3]*hh[3] + wc[4]*hh[4];
    }
    g_emb[(size_t)g*DENSE + o*28 + l] = fmaxf(acc, 0.f);
  }
}

/* ---------------- fc1 (39424 -> 128) + relu ----------------------------------- */
__global__ void k_fc1(const float* __restrict__ fw1, const float* __restrict__ fb1) {
  int o = blockIdx.x, tid = threadIdx.x;
  float acc = 0.f;
  const float* w = fw1 + (size_t)o*FC1IN;
  for (int i = tid; i < FC1IN; i += 256) acc += g_emb[i]*w[i];
  __shared__ float sh[8];
  #pragma unroll
  for (int d = 16; d; d >>= 1) acc += __shfl_down_sync(0xffffffffu, acc, d);
  if ((tid & 31) == 0) sh[tid >> 5] = acc;
  __syncthreads();
  if (tid < 8) {
    float v = sh[tid];
    #pragma unroll
    for (int d = 4; d; d >>= 1) v += __shfl_down_sync(0x000000ffu, v, d);
    if (tid == 0) g_out128[o] = fmaxf(v + fb1[o], 0.f);
  }
}

/* ---------------- fc2 (128 -> 10) --------------------------------------------- */
__global__ void k_fc2(const float* __restrict__ fw2, const float* __restrict__ fb2,
                      float* __restrict__ out) {
  int t = threadIdx.x >> 5, lane = threadIdx.x & 31;
  if (t >= 10) return;
  float acc = 0.f;
  for (int i = lane; i < 128; i += 32) acc += g_out128[i]*fw2[t*128 + i];
  #pragma unroll
  for (int d = 16; d; d >>= 1) acc += __shfl_down_sync(0xffffffffu, acc, d);
  if (lane == 0) out[t] = acc + fb2[t];
}

/* ---------------- host orchestration ------------------------------------------ */
#define GEMM_DSMEM 65536

extern "C" void kernel_launch(void* const* d_in, const int* in_sizes, int n_in,
                              void* d_out, int out_size) {
  const float* x     = (const float*)d_in[0];
  const int*   ei    = (const int*)  d_in[1];
  const int*   batch = (const int*)  d_in[2];
  const float* W1 = (const float*)d_in[3],  *b1  = (const float*)d_in[4];
  const float* W2 = (const float*)d_in[5],  *b2  = (const float*)d_in[6];
  const float* W3 = (const float*)d_in[7],  *b3  = (const float*)d_in[8];
  const float* W4 = (const float*)d_in[9],  *b4  = (const float*)d_in[10];
  const float* cw5= (const float*)d_in[11], *cb5 = (const float*)d_in[12];
  const float* cw6= (const float*)d_in[13], *cb6 = (const float*)d_in[14];
  const float* fw1= (const float*)d_in[15], *fb1 = (const float*)d_in[16];
  const float* fw2= (const float*)d_in[17], *fb2 = (const float*)d_in[18];
  float* logits = (float*)d_out;

  cudaFuncSetAttribute(k_gemm, cudaFuncAttributeMaxDynamicSharedMemorySize, GEMM_DSMEM);

  const int TB = 256;
  const int nbN  = (NN + TB - 1)/TB;
  const int nbE  = (NE + TB - 1)/TB;
  const int nbW  = (NN*32 + TB - 1)/TB;
  const int nbSc = (NN + 1023)/1024;
  const int gemmGrid = NN/128;   /* 3125, exact */

  k_init      <<<nbN, TB>>>();
  k_edge_count<<<nbE, TB>>>(ei);
  k_dis       <<<nbN, TB>>>();
  /* launch 4: GEMM-1 — lands in the ncu profiling slot */
  k_gemm      <<<gemmGrid, 256, GEMM_DSMEM>>>(x, 0, W1, FIN);
  k_scan1     <<<nbSc, 1024>>>();
  k_scan2     <<<1, 1024>>>(nbSc);
  k_scan3     <<<nbN, TB>>>();
  k_scatter   <<<nbE, TB>>>(ei);
  k_gcount    <<<nbN, TB>>>(batch);
  k_gstart    <<<1, 32>>>();

  k_agg_half <<<nbW, TB>>>(b1, 1, 0, nullptr);
  k_agg_half <<<nbW, TB>>>(b1, 1, 1, nullptr);
  k_gemm     <<<gemmGrid, 256, GEMM_DSMEM>>>(nullptr, 1, W2, EMB);
  k_agg_half <<<nbW, TB>>>(b2, 2, 0, nullptr);
  k_agg_half <<<nbW, TB>>>(b2, 2, 1, nullptr);
  k_gemm     <<<gemmGrid, 256, GEMM_DSMEM>>>(nullptr, 2, W3, EMB);
  k_agg_half <<<nbW, TB>>>(b3, 3, 0, W4);
  k_agg_half <<<nbW, TB>>>(b3, 3, 1, W4);
  k_agg4     <<<nbN, TB>>>(b4);

  k_select <<<NG, 1024>>>();
  k_conv5  <<<NG*SORTK, 128>>>(cw5, cb5);
  k_conv6  <<<NG, 128>>>(cw6, cb6);
  k_fc1    <<<128, 256>>>(fw1, fb1);
  k_fc2    <<<1, 320>>>(fw2, fb2, logits);
}

// round 9
// speedup vs baseline: 1.3391x; 1.3391x over previous
#include <cuda_runtime.h>
#include <math.h>

#define NN    400000
#define NE    1600000
#define FIN   100
#define EMB   128
#define SORTK 64
#define NG    11
#define DCAT  385
#define DENSE 3584
#define FC1IN 39424

typedef unsigned long long ull;
typedef unsigned int uint;

/* ---------------- scratch (static device memory; no allocations) ------------- */
__device__ float g_h [NN*EMB];
__device__ float g_x1[NN*EMB];
__device__ float g_x2[NN*EMB];
__device__ float g_x3[NN*EMB];
__device__ float g_x4[NN];
__device__ float g_h4[NN];
__device__ float g_dis[NN];
__device__ int   g_cnt[NN];
__device__ int   g_off[NN];
__device__ int   g_cur[NN];
__device__ int2  g_csr[NE];
__device__ int   g_bsum[1024];
__device__ int   g_gcnt[NG];
__device__ int   g_gstart[NG+1];
__device__ int   g_sel[NG*SORTK];
__device__ float g_h5[NG*64*SORTK];
__device__ float g_emb[FC1IN];
__device__ float g_out128[128];

__device__ __forceinline__ float* bufById(int id) {
  return (id==1) ? g_x1 : (id==2) ? g_x2 : g_x3;
}

/* ---------------- f32x2 packed helpers ---------------------------------------- */
__device__ __forceinline__ void ffma2(ull& d, ull a, ull b) {
  asm("fma.rn.f32x2 %0, %1, %2, %0;" : "+l"(d) : "l"(a), "l"(b));
}
__device__ __forceinline__ ull dup2(float x) {
  ull r; asm("mov.b64 %0, {%1, %1};" : "=l"(r) : "f"(x)); return r;
}
__device__ __forceinline__ float2 unpack2(ull v) {
  float2 f; asm("mov.b64 {%0, %1}, %2;" : "=f"(f.x), "=f"(f.y) : "l"(v)); return f;
}

/* ---------------- init / degree / CSR build ---------------------------------- */
__global__ void k_init() {
  int i = blockIdx.x*blockDim.x + threadIdx.x;
  if (i < NN) { g_cnt[i] = 0; g_cur[i] = 0; }
  if (i < NG) g_gcnt[i] = 0;
  if (i < NG*SORTK) g_sel[i] = -1;
}

__global__ void k_edge_count(const int* __restrict__ ei) {
  int e = blockIdx.x*blockDim.x + threadIdx.x;
  if (e >= NE) return;
  int s = ei[e], d = ei[NE + e];
  if (s != d) atomicAdd(&g_cnt[d], 1);
}

__global__ void k_dis() {
  int i = blockIdx.x*blockDim.x + threadIdx.x;
  if (i < NN) g_dis[i] = rsqrtf((float)g_cnt[i] + 1.0f);
}

__global__ void k_scan1() {
  __shared__ int sh[1024];
  int t = threadIdx.x;
  int i = blockIdx.x*1024 + t;
  int v = (i < NN) ? g_cnt[i] : 0;
  sh[t] = v; __syncthreads();
  for (int d = 1; d < 1024; d <<= 1) {
    int u = (t >= d) ? sh[t-d] : 0;
    __syncthreads();
    sh[t] += u;
    __syncthreads();
  }
  if (i < NN) g_off[i] = sh[t] - v;
  if (t == 1023) g_bsum[blockIdx.x] = sh[1023];
}

__global__ void k_scan2(int nb) {
  __shared__ int sh[1024];
  int t = threadIdx.x;
  int v = (t < nb) ? g_bsum[t] : 0;
  sh[t] = v; __syncthreads();
  for (int d = 1; d < 1024; d <<= 1) {
    int u = (t >= d) ? sh[t-d] : 0;
    __syncthreads();
    sh[t] += u;
    __syncthreads();
  }
  if (t < nb) g_bsum[t] = sh[t] - v;
}

__global__ void k_scan3() {
  int i = blockIdx.x*blockDim.x + threadIdx.x;
  if (i < NN) g_off[i] += g_bsum[i >> 10];
}

__global__ void k_scatter(const int* __restrict__ ei) {
  int e = blockIdx.x*blockDim.x + threadIdx.x;
  if (e >= NE) return;
  int s = ei[e], d = ei[NE + e];
  if (s != d) {
    int p = g_off[d] + atomicAdd(&g_cur[d], 1);
    float w = g_dis[s]*g_dis[d];
    g_csr[p] = make_int2(s, __float_as_int(w));
  }
}

__global__ void k_gcount(const int* __restrict__ batch) {
  __shared__ int loc[NG];
  if (threadIdx.x < NG) loc[threadIdx.x] = 0;
  __syncthreads();
  int i = blockIdx.x*blockDim.x + threadIdx.x;
  if (i < NN) atomicAdd(&loc[batch[i]], 1);
  __syncthreads();
  if (threadIdx.x < NG) atomicAdd(&g_gcnt[threadIdx.x], loc[threadIdx.x]);
}

__global__ void k_gstart() {
  if (threadIdx.x == 0 && blockIdx.x == 0) {
    int a = 0;
    for (int g = 0; g < NG; ++g) { g_gstart[g] = a; a += g_gcnt[g]; }
    g_gstart[NG] = a;
  }
}

/* ---------------- GEMM: H[nrows,128] = X[nrows,K] @ W[K,128] (FFMA2) ---------- */
__global__ __launch_bounds__(256, 2) void k_gemm(const float* __restrict__ Xext, int xbuf,
                                                 const float* __restrict__ W, int K) {
  __shared__ float Xs[128*32];
  __shared__ float Ws[32*128];
  const float* __restrict__ X = Xext ? Xext : bufById(xbuf);
  const int tid = threadIdx.x;
  const int tr  = tid >> 4;
  const int tc  = tid & 15;
  const int r0  = tr * 8;
  const int c0  = tc * 8;
  const int row0 = blockIdx.x * 128;

  ull acc[8][4];
  #pragma unroll
  for (int r = 0; r < 8; ++r)
    #pragma unroll
    for (int j = 0; j < 4; ++j) acc[r][j] = 0ull;

  for (int k0 = 0; k0 < K; k0 += 32) {
    const int kc = min(32, K - k0);
    {
      const float4* src = (const float4*)(W + (size_t)k0*128);
      float4* dst = (float4*)Ws;
      for (int i = tid; i < kc*32; i += 256) dst[i] = src[i];
    }
    if (kc == 32) {
      for (int i = tid; i < 128*32; i += 256) {
        int r = i >> 5, k = i & 31;
        Xs[i] = X[(size_t)(row0 + r)*K + k0 + k];
      }
    } else {
      for (int i = tid; i < 128*kc; i += 256) {
        int r = i / kc, k = i - r*kc;
        Xs[r*32 + k] = X[(size_t)(row0 + r)*K + k0 + k];
      }
    }
    __syncthreads();

    #pragma unroll 8
    for (int k = 0; k < kc; ++k) {
      ull w[4];
      const ull* wp = (const ull*)(Ws + k*128 + c0);
      w[0] = wp[0]; w[1] = wp[1]; w[2] = wp[2]; w[3] = wp[3];
      #pragma unroll
      for (int r = 0; r < 8; ++r) {
        ull xd = dup2(Xs[(r0 + r)*32 + k]);
        ffma2(acc[r][0], xd, w[0]);
        ffma2(acc[r][1], xd, w[1]);
        ffma2(acc[r][2], xd, w[2]);
        ffma2(acc[r][3], xd, w[3]);
      }
    }
    __syncthreads();
  }

  #pragma unroll
  for (int r = 0; r < 8; ++r) {
    int gr = row0 + r0 + r;
    float2 a0 = unpack2(acc[r][0]), a1 = unpack2(acc[r][1]);
    float2 a2 = unpack2(acc[r][2]), a3 = unpack2(acc[r][3]);
    *(float4*)&g_h[(size_t)gr*EMB + c0]     = make_float4(a0.x, a0.y, a1.x, a1.y);
    *(float4*)&g_h[(size_t)gr*EMB + c0 + 4] = make_float4(a2.x, a2.y, a3.x, a3.y);
  }
}

/* ---------------- aggregation + self term + bias + tanh (+ fused h4) ---------- */
__global__ void k_agg_tanh(const float* __restrict__ bias, int outId,
                           const float* __restrict__ W4) {
  int n = (blockIdx.x*blockDim.x + threadIdx.x) >> 5;
  if (n >= NN) return;
  int lane = threadIdx.x & 31;
  const int co = lane*4;

  int b = g_off[n], e = b + g_cnt[n];
  float di = g_dis[n];
  float4 self = *(const float4*)(g_h + (size_t)n*EMB + co);

  float4 acc = make_float4(0.f,0.f,0.f,0.f);
  int j = b;
  for (; j + 4 <= e; j += 4) {
    int2 e0 = g_csr[j],   e1 = g_csr[j+1];
    int2 e2 = g_csr[j+2], e3 = g_csr[j+3];
    float4 h0 = *(const float4*)(g_h + (size_t)e0.x*EMB + co);
    float4 h1 = *(const float4*)(g_h + (size_t)e1.x*EMB + co);
    float4 h2 = *(const float4*)(g_h + (size_t)e2.x*EMB + co);
    float4 h3 = *(const float4*)(g_h + (size_t)e3.x*EMB + co);
    float w0 = __int_as_float(e0.y), w1 = __int_as_float(e1.y);
    float w2 = __int_as_float(e2.y), w3 = __int_as_float(e3.y);
    acc.x += w0*h0.x + w1*h1.x + w2*h2.x + w3*h3.x;
    acc.y += w0*h0.y + w1*h1.y + w2*h2.y + w3*h3.y;
    acc.z += w0*h0.z + w1*h1.z + w2*h2.z + w3*h3.z;
    acc.w += w0*h0.w + w1*h1.w + w2*h2.w + w3*h3.w;
  }
  for (; j < e; ++j) {
    int2 ee = g_csr[j];
    float w = __int_as_float(ee.y);
    float4 hv = *(const float4*)(g_h + (size_t)ee.x*EMB + co);
    acc.x += w*hv.x; acc.y += w*hv.y; acc.z += w*hv.z; acc.w += w*hv.w;
  }

  float sn = di*di;
  float4 bv = *(const float4*)(bias + co);
  float4 o;
  o.x = tanhf(acc.x + sn*self.x + bv.x);
  o.y = tanhf(acc.y + sn*self.y + bv.y);
  o.z = tanhf(acc.z + sn*self.z + bv.z);
  o.w = tanhf(acc.w + sn*self.w + bv.w);
  *(float4*)(bufById(outId) + (size_t)n*EMB + co) = o;

  if (W4) {
    float4 wv = *(const float4*)(W4 + co);
    float a = o.x*wv.x + o.y*wv.y + o.z*wv.z + o.w*wv.w;
    #pragma unroll
    for (int d = 16; d; d >>= 1) a += __shfl_down_sync(0xffffffffu, a, d);
    if (lane == 0) g_h4[n] = a;
  }
}

/* ---------------- layer 4 aggregation (scalar) -------------------------------- */
__global__ void k_agg4(const float* __restrict__ b4) {
  int n = blockIdx.x*blockDim.x + threadIdx.x;
  if (n >= NN) return;
  float acc = 0.f;
  int b = g_off[n], e = b + g_cnt[n];
  int j = b;
  for (; j + 2 <= e; j += 2) {
    int2 e0 = g_csr[j], e1 = g_csr[j+1];
    float v0 = g_h4[e0.x], v1 = g_h4[e1.x];
    acc += __int_as_float(e0.y)*v0 + __int_as_float(e1.y)*v1;
  }
  if (j < e) {
    int2 e0 = g_csr[j];
    acc += __int_as_float(e0.y)*g_h4[e0.x];
  }
  float di = g_dis[n];
  g_x4[n] = tanhf(acc + g_h4[n]*di*di + b4[0]);
}

/* ---------------- per-graph exact top-64: byte-radix histogram select --------- */
__device__ __forceinline__ unsigned keyOf(float f) {
  unsigned u = __float_as_uint(f);
  return (u & 0x80000000u) ? ~u : (u | 0x80000000u);
}

__global__ void k_select() {
  const int g = blockIdx.x;
  const int s = g_gstart[g], e = g_gstart[g+1];
  const int n = e - s;
  const int tid = threadIdx.x;
  const int NT = blockDim.x;   /* 1024 */

  __shared__ int      selIdx[SORTK];
  __shared__ unsigned selKey[SORTK];
  __shared__ int      hist[256];
  __shared__ unsigned shPrefix;
  __shared__ int      shRem, shCg;

  if (tid < SORTK) { selIdx[tid] = -1; selKey[tid] = 0u; }
  if (tid == 0)    { shPrefix = 0u; shRem = SORTK; shCg = 0; }
  __syncthreads();

  if (n <= SORTK) {
    if (tid < n) { selIdx[tid] = s + tid; selKey[tid] = keyOf(g_x4[s+tid]); }
    __syncthreads();
  } else {
    /* byte-wise MSB radix: 4 histogram passes find the 64th-largest key */
    for (int byte = 3; byte >= 0; --byte) {
      if (tid < 256) hist[tid] = 0;
      __syncthreads();
      const int sh = byte*8;
      const unsigned maskHigh = (byte == 3) ? 0u : ~((1u << (sh + 8)) - 1u);
      const unsigned pref = shPrefix;
      for (int i = s + tid; i < e; i += NT) {
        unsigned k = keyOf(g_x4[i]);
        if ((k & maskHigh) == pref)
          atomicAdd(&hist[(k >> sh) & 255u], 1);
      }
      __syncthreads();
      if (tid == 0) {
        int rem = shRem, cum = 0, bin = 0;
        for (int b2 = 255; b2 >= 0; --b2) {
          if (cum + hist[b2] >= rem) { bin = b2; break; }
          cum += hist[b2];
        }
        shRem = rem - cum;
        shPrefix = shPrefix | ((unsigned)bin << sh);
      }
      __syncthreads();
    }
    unsigned Tk = shPrefix;
    /* strictly greater than threshold (count <= 63 by construction) */
    for (int i = s + tid; i < e; i += NT) {
      unsigned k = keyOf(g_x4[i]);
      if (k > Tk) {
        int p = atomicAdd(&shCg, 1);
        selIdx[p] = i; selKey[p] = k;
      }
    }
    __syncthreads();
    int cg = shCg;
    int need = SORTK - cg;
    /* ties at threshold: take smallest indices (stable-sort semantics) */
    for (int i = s + tid; i < e; i += NT) {
      if (keyOf(g_x4[i]) == Tk) {
        int r = 0;
        for (int j = s; j < i; ++j) r += (keyOf(g_x4[j]) == Tk) ? 1 : 0;
        if (r < need) { selIdx[cg + r] = i; selKey[cg + r] = Tk; }
      }
    }
    __syncthreads();
  }

  /* rank-sort the <=64 selected: key desc, index asc */
  if (tid < SORTK) {
    int mi = selIdx[tid];
    if (mi >= 0) {
      unsigned mk = selKey[tid];
      int r = 0;
      for (int j = 0; j < SORTK; ++j) {
        int ij = selIdx[j]; if (ij < 0) continue;
        unsigned kj = selKey[j];
        if (kj > mk || (kj == mk && ij < mi)) ++r;
      }
      g_sel[g*SORTK + r] = mi;
    }
  }
}

/* ---------------- conv5 (385 -> 64 per sorted row) + relu --------------------- */
__global__ void k_conv5(const float* __restrict__ cw5, const float* __restrict__ cb5) {
  __shared__ float row[DCAT];
  int g = blockIdx.x / SORTK, k = blockIdx.x % SORTK;
  int m = g_sel[g*SORTK + k];
  int tid = threadIdx.x;
  for (int d = tid; d < DCAT; d += 128) {
    float v = 0.f;
    if (m >= 0) {
      if      (d < 128) v = g_x1[(size_t)m*EMB + d];
      else if (d < 256) v = g_x2[(size_t)m*EMB + d - 128];
      else if (d < 384) v = g_x3[(size_t)m*EMB + d - 256];
      else              v = g_x4[m];
    }
    row[d] = v;
  }
  __syncthreads();
  if (tid < 64) {
    float acc = cb5[tid];
    const float* w = cw5 + tid*DCAT;
    for (int d = 0; d < DCAT; ++d) acc += w[d]*row[d];
    g_h5[((size_t)g*64 + tid)*SORTK + k] = fmaxf(acc, 0.f);
  }
}

/* ---------------- maxpool(2) + conv6(k=5) + relu -> emb ----------------------- */
__global__ void k_conv6(const float* __restrict__ cw6, const float* __restrict__ cb6) {
  __shared__ float hp[64*32];
  int g = blockIdx.x, tid = threadIdx.x;
  for (int i = tid; i < 64*32; i += 128) {
    int ci = i >> 5, j = i & 31;
    const float* hr = g_h5 + ((size_t)g*64 + ci)*SORTK + 2*j;
    hp[ci*32 + j] = fmaxf(hr[0], hr[1]);
  }
  __syncthreads();
  int o = tid;
  const float* w = cw6 + (size_t)o*64*5;
  for (int l = 0; l < 28; ++l) {
    float acc = cb6[o];
    for (int ci = 0; ci < 64; ++ci) {
      const float* hh = hp + ci*32 + l;
      const float* wc = w + ci*5;
      acc += wc[0]*hh[0] + wc[1]*hh[1] + wc[2]*hh[2] + wc[3]*hh[3] + wc[4]*hh[4];
    }
    g_emb[(size_t)g*DENSE + o*28 + l] = fmaxf(acc, 0.f);
  }
}

/* ---------------- fc1 (39424 -> 128) + relu ----------------------------------- */
__global__ void k_fc1(const float* __restrict__ fw1, const float* __restrict__ fb1) {
  int o = blockIdx.x, tid = threadIdx.x;
  float acc = 0.f;
  const float* w = fw1 + (size_t)o*FC1IN;
  for (int i = tid; i < FC1IN; i += 256) acc += g_emb[i]*w[i];
  __shared__ float sh[8];
  #pragma unroll
  for (int d = 16; d; d >>= 1) acc += __shfl_down_sync(0xffffffffu, acc, d);
  if ((tid & 31) == 0) sh[tid >> 5] = acc;
  __syncthreads();
  if (tid < 8) {
    float v = sh[tid];
    #pragma unroll
    for (int d = 4; d; d >>= 1) v += __shfl_down_sync(0x000000ffu, v, d);
    if (tid == 0) g_out128[o] = fmaxf(v + fb1[o], 0.f);
  }
}

/* ---------------- fc2 (128 -> 10) --------------------------------------------- */
__global__ void k_fc2(const float* __restrict__ fw2, const float* __restrict__ fb2,
                      float* __restrict__ out) {
  int t = threadIdx.x >> 5, lane = threadIdx.x & 31;
  if (t >= 10) return;
  float acc = 0.f;
  for (int i = lane; i < 128; i += 32) acc += g_out128[i]*fw2[t*128 + i];
  #pragma unroll
  for (int d = 16; d; d >>= 1) acc += __shfl_down_sync(0xffffffffu, acc, d);
  if (lane == 0) out[t] = acc + fb2[t];
}

/* ---------------- host orchestration ------------------------------------------ */
extern "C" void kernel_launch(void* const* d_in, const int* in_sizes, int n_in,
                              void* d_out, int out_size) {
  const float* x     = (const float*)d_in[0];
  const int*   ei    = (const int*)  d_in[1];
  const int*   batch = (const int*)  d_in[2];
  const float* W1 = (const float*)d_in[3],  *b1  = (const float*)d_in[4];
  const float* W2 = (const float*)d_in[5],  *b2  = (const float*)d_in[6];
  const float* W3 = (const float*)d_in[7],  *b3  = (const float*)d_in[8];
  const float* W4 = (const float*)d_in[9],  *b4  = (const float*)d_in[10];
  const float* cw5= (const float*)d_in[11], *cb5 = (const float*)d_in[12];
  const float* cw6= (const float*)d_in[13], *cb6 = (const float*)d_in[14];
  const float* fw1= (const float*)d_in[15], *fb1 = (const float*)d_in[16];
  const float* fw2= (const float*)d_in[17], *fb2 = (const float*)d_in[18];
  float* logits = (float*)d_out;

  const int TB = 256;
  const int nbN  = (NN + TB - 1)/TB;
  const int nbE  = (NE + TB - 1)/TB;
  const int nbW  = (NN*32 + TB - 1)/TB;
  const int nbSc = (NN + 1023)/1024;
  const int gemmGrid = NN/128;   /* 3125, exact */

  k_init      <<<nbN, TB>>>();
  k_edge_count<<<nbE, TB>>>(ei);
  k_dis       <<<nbN, TB>>>();
  /* launch 4: GEMM-1 — lands in the ncu profiling slot */
  k_gemm      <<<gemmGrid, 256>>>(x, 0, W1, FIN);
  k_scan1     <<<nbSc, 1024>>>();
  k_scan2     <<<1, 1024>>>(nbSc);
  k_scan3     <<<nbN, TB>>>();
  k_scatter   <<<nbE, TB>>>(ei);
  k_gcount    <<<nbN, TB>>>(batch);
  k_gstart    <<<1, 32>>>();

  k_agg_tanh <<<nbW, TB>>>(b1, 1, nullptr);
  k_gemm     <<<gemmGrid, 256>>>(nullptr, 1, W2, EMB);
  k_agg_tanh <<<nbW, TB>>>(b2, 2, nullptr);
  k_gemm     <<<gemmGrid, 256>>>(nullptr, 2, W3, EMB);
  k_agg_tanh <<<nbW, TB>>>(b3, 3, W4);
  k_agg4     <<<nbN, TB>>>(b4);

  k_select <<<NG, 1024>>>();
  k_conv5  <<<NG*SORTK, 128>>>(cw5, cb5);
  k_conv6  <<<NG, 128>>>(cw6, cb6);
  k_fc1    <<<128, 256>>>(fw1, fb1);
  k_fc2    <<<1, 320>>>(fw2, fb2, logits);
}